// round 1
// baseline (speedup 1.0000x reference)
#include <cuda_runtime.h>
#include <math.h>

// Problem constants
#define BATCH 4
#define SEQ   4096
#define DIM   1024
#define HDIM  64

// Scratch for Q, K, V projections: 3 x [B*T, HD] fp32 = 12 MB (device globals, no alloc)
__device__ float g_QKV[3][(size_t)BATCH * SEQ * HDIM];

// ---------------------------------------------------------------------------
// Kernel 1: QKV projection.  out[m][n] = sum_k x[m][k] * W[n][k]
// M = B*T = 16384, N = 64, K = 1024.  grid = (M/64, 3), block = 256.
// 64x64 output tile, BK=16, 4x4 microtile per thread.
// ---------------------------------------------------------------------------
__global__ __launch_bounds__(256) void qkv_kernel(
    const float* __restrict__ x,
    const float* __restrict__ wq,
    const float* __restrict__ wk,
    const float* __restrict__ wv)
{
    // smem stride 68: 16B-aligned rows (68*4=272=17*16), bank shift 4/row
    __shared__ __align__(16) float Xs[16 * 68];   // [kk][m] transposed
    __shared__ __align__(16) float Ws[16 * 68];   // [kk][n] transposed

    const float* W = (blockIdx.y == 0) ? wq : ((blockIdx.y == 1) ? wk : wv);
    float* out = g_QKV[blockIdx.y];

    const int tid = threadIdx.x;
    const int rg  = tid >> 4;       // 0..15: row group (4 rows each)
    const int cg  = tid & 15;       // 0..15: col group (4 cols each)
    const int m0  = blockIdx.x * 64;

    // loading: 64 rows x 16 k per tile; each thread: 1 float4 from x, 1 from W
    const int lrow = tid >> 2;          // 0..63
    const int lk   = (tid & 3) * 4;     // 0,4,8,12

    float acc[4][4] = {};

    for (int k0 = 0; k0 < DIM; k0 += 16) {
        float4 xv = *(const float4*)(x + (size_t)(m0 + lrow) * DIM + k0 + lk);
        Xs[(lk + 0) * 68 + lrow] = xv.x;
        Xs[(lk + 1) * 68 + lrow] = xv.y;
        Xs[(lk + 2) * 68 + lrow] = xv.z;
        Xs[(lk + 3) * 68 + lrow] = xv.w;
        float4 wv4 = *(const float4*)(W + (size_t)lrow * DIM + k0 + lk);
        Ws[(lk + 0) * 68 + lrow] = wv4.x;
        Ws[(lk + 1) * 68 + lrow] = wv4.y;
        Ws[(lk + 2) * 68 + lrow] = wv4.z;
        Ws[(lk + 3) * 68 + lrow] = wv4.w;
        __syncthreads();

        #pragma unroll
        for (int kk = 0; kk < 16; kk++) {
            float4 a4 = *(const float4*)(Xs + kk * 68 + rg * 4);
            float4 b4 = *(const float4*)(Ws + kk * 68 + cg * 4);
            float a[4] = {a4.x, a4.y, a4.z, a4.w};
            float b[4] = {b4.x, b4.y, b4.z, b4.w};
            #pragma unroll
            for (int i = 0; i < 4; i++)
                #pragma unroll
                for (int j = 0; j < 4; j++)
                    acc[i][j] = fmaf(a[i], b[j], acc[i][j]);
        }
        __syncthreads();
    }

    #pragma unroll
    for (int i = 0; i < 4; i++) {
        float4 o = {acc[i][0], acc[i][1], acc[i][2], acc[i][3]};
        *(float4*)(out + (size_t)(m0 + rg * 4 + i) * HDIM + cg * 4) = o;
    }
}

// ---------------------------------------------------------------------------
// Kernel 2: flash attention.  grid = (T/64, B), block = 256.
// Q tile 64, KV tile 64, online softmax, 4x4 microtiles.
// smem: Qs[d][i], Ks[d][j], Vs[j][n], Ps[i][j], all stride 68.
// ---------------------------------------------------------------------------
__global__ __launch_bounds__(256) void attn_kernel(float* __restrict__ out)
{
    extern __shared__ float sm[];
    float* Qs = sm;                 // [64][68]  (d-major, transposed)
    float* Ks = sm + 64 * 68;       // [64][68]  (d-major, transposed)
    float* Vs = sm + 2 * 64 * 68;   // [64][68]  (j-major, natural)
    float* Ps = sm + 3 * 64 * 68;   // [64][68]  (i-major, natural)

    const int tid = threadIdx.x;
    const int rg  = tid >> 4;       // query-row group
    const int cg  = tid & 15;       // key-col / hd-col group
    const int b   = blockIdx.y;
    const int q0  = blockIdx.x * 64;

    const float* Qg = g_QKV[0] + (size_t)b * SEQ * HDIM;
    const float* Kg = g_QKV[1] + (size_t)b * SEQ * HDIM;
    const float* Vg = g_QKV[2] + (size_t)b * SEQ * HDIM;

    const int lrow = tid >> 2;          // 0..63
    const int lc   = (tid & 3) * 16;    // 0,16,32,48

    // Load Q tile transposed, fold in 1/sqrt(HD) = 0.125
    #pragma unroll
    for (int i = 0; i < 4; i++) {
        float4 v = *(const float4*)(Qg + (size_t)(q0 + lrow) * HDIM + lc + i * 4);
        Qs[(lc + i * 4 + 0) * 68 + lrow] = v.x * 0.125f;
        Qs[(lc + i * 4 + 1) * 68 + lrow] = v.y * 0.125f;
        Qs[(lc + i * 4 + 2) * 68 + lrow] = v.z * 0.125f;
        Qs[(lc + i * 4 + 3) * 68 + lrow] = v.w * 0.125f;
    }

    float acc[4][4] = {};
    float m[4], l[4];
    #pragma unroll
    for (int i = 0; i < 4; i++) { m[i] = -1e30f; l[i] = 0.0f; }

    for (int kt = 0; kt < SEQ; kt += 64) {
        __syncthreads();   // Q stores visible (iter 0); prev PV reads of Ks/Vs done
        // Load K tile transposed, V tile natural
        #pragma unroll
        for (int i = 0; i < 4; i++) {
            float4 kv = *(const float4*)(Kg + (size_t)(kt + lrow) * HDIM + lc + i * 4);
            Ks[(lc + i * 4 + 0) * 68 + lrow] = kv.x;
            Ks[(lc + i * 4 + 1) * 68 + lrow] = kv.y;
            Ks[(lc + i * 4 + 2) * 68 + lrow] = kv.z;
            Ks[(lc + i * 4 + 3) * 68 + lrow] = kv.w;
            float4 vv = *(const float4*)(Vg + (size_t)(kt + lrow) * HDIM + lc + i * 4);
            *(float4*)(Vs + lrow * 68 + lc + i * 4) = vv;
        }
        __syncthreads();

        // S = (Q * scale) @ K^T  (64x64, 4x4 per thread)
        float s[4][4] = {};
        #pragma unroll 8
        for (int d = 0; d < 64; d++) {
            float4 q4 = *(const float4*)(Qs + d * 68 + rg * 4);
            float4 k4 = *(const float4*)(Ks + d * 68 + cg * 4);
            float qa[4] = {q4.x, q4.y, q4.z, q4.w};
            float ka[4] = {k4.x, k4.y, k4.z, k4.w};
            #pragma unroll
            for (int i = 0; i < 4; i++)
                #pragma unroll
                for (int j = 0; j < 4; j++)
                    s[i][j] = fmaf(qa[i], ka[j], s[i][j]);
        }

        // Online softmax per row (16-lane groups share a row set; shfl reduce)
        #pragma unroll
        for (int i = 0; i < 4; i++) {
            float rm = fmaxf(fmaxf(s[i][0], s[i][1]), fmaxf(s[i][2], s[i][3]));
            rm = fmaxf(rm, __shfl_xor_sync(0xffffffffu, rm, 1));
            rm = fmaxf(rm, __shfl_xor_sync(0xffffffffu, rm, 2));
            rm = fmaxf(rm, __shfl_xor_sync(0xffffffffu, rm, 4));
            rm = fmaxf(rm, __shfl_xor_sync(0xffffffffu, rm, 8));
            float newm = fmaxf(m[i], rm);
            float corr = __expf(m[i] - newm);
            m[i] = newm;
            float rs = 0.0f;
            #pragma unroll
            for (int j = 0; j < 4; j++) {
                s[i][j] = __expf(s[i][j] - newm);
                rs += s[i][j];
            }
            rs += __shfl_xor_sync(0xffffffffu, rs, 1);
            rs += __shfl_xor_sync(0xffffffffu, rs, 2);
            rs += __shfl_xor_sync(0xffffffffu, rs, 4);
            rs += __shfl_xor_sync(0xffffffffu, rs, 8);
            l[i] = l[i] * corr + rs;
            #pragma unroll
            for (int j = 0; j < 4; j++) acc[i][j] *= corr;
        }

        // Store P (natural [i][j], float4 along j -> conflict-free)
        #pragma unroll
        for (int i = 0; i < 4; i++) {
            float4 pv = {s[i][0], s[i][1], s[i][2], s[i][3]};
            *(float4*)(Ps + (rg * 4 + i) * 68 + cg * 4) = pv;
        }
        __syncthreads();

        // O += P @ V   (P read as broadcast scalars, V as float4)
        #pragma unroll 8
        for (int j = 0; j < 64; j++) {
            float4 v4 = *(const float4*)(Vs + j * 68 + cg * 4);
            float va[4] = {v4.x, v4.y, v4.z, v4.w};
            float p0 = Ps[(rg * 4 + 0) * 68 + j];
            float p1 = Ps[(rg * 4 + 1) * 68 + j];
            float p2 = Ps[(rg * 4 + 2) * 68 + j];
            float p3 = Ps[(rg * 4 + 3) * 68 + j];
            #pragma unroll
            for (int n = 0; n < 4; n++) {
                acc[0][n] = fmaf(p0, va[n], acc[0][n]);
                acc[1][n] = fmaf(p1, va[n], acc[1][n]);
                acc[2][n] = fmaf(p2, va[n], acc[2][n]);
                acc[3][n] = fmaf(p3, va[n], acc[3][n]);
            }
        }
    }

    // Epilogue: normalize, write out [B, T, HD]
    #pragma unroll
    for (int i = 0; i < 4; i++) {
        float inv = 1.0f / l[i];
        float4 o = {acc[i][0] * inv, acc[i][1] * inv, acc[i][2] * inv, acc[i][3] * inv};
        *(float4*)(out + ((size_t)b * SEQ + q0 + rg * 4 + i) * HDIM + cg * 4) = o;
    }
}

// ---------------------------------------------------------------------------
extern "C" void kernel_launch(void* const* d_in, const int* in_sizes, int n_in,
                              void* d_out, int out_size)
{
    const float* x  = (const float*)d_in[0];
    const float* wq = (const float*)d_in[1];
    const float* wk = (const float*)d_in[2];
    const float* wv = (const float*)d_in[3];
    float* out = (float*)d_out;

    // QKV projections: grid (M/64, 3)
    qkv_kernel<<<dim3((BATCH * SEQ) / 64, 3), 256>>>(x, wq, wk, wv);

    // Flash attention: grid (T/64, B), 68 KB dynamic smem (opt-in > 48KB)
    const int smem = 4 * 64 * 68 * (int)sizeof(float);  // 69632
    cudaFuncSetAttribute(attn_kernel, cudaFuncAttributeMaxDynamicSharedMemorySize, smem);
    attn_kernel<<<dim3(SEQ / 64, BATCH), 256, smem>>>(out);
}

// round 2
// speedup vs baseline: 1.2226x; 1.2226x over previous
#include <cuda_runtime.h>
#include <math.h>

// Problem constants
#define BATCH 4
#define SEQ   4096
#define DIM   1024
#define HDIM  64

#define SSTR   68            // smem row stride in floats (16B aligned, +4 bank shift)
#define TILE_F (64 * SSTR)   // floats per 64-row tile = 4352

// Scratch for Q, K, V projections (device globals, no alloc)
__device__ float g_QKV[3][(size_t)BATCH * SEQ * HDIM];

// ---------------------------------------------------------------------------
// QKV projection: out[m][n] = sum_k x[m][k] * W[n][k].  M=16384, N=64, K=1024.
// Block 128 = 2 teams x 64 threads. Team tile: 64 rows x 64 cols, 8x8 microtile.
// W tile shared between teams. grid = (M/128, 3).
// ---------------------------------------------------------------------------
__global__ __launch_bounds__(128) void qkv_kernel(
    const float* __restrict__ x,
    const float* __restrict__ wq,
    const float* __restrict__ wk,
    const float* __restrict__ wv)
{
    __shared__ __align__(16) float Ws[16 * SSTR];      // [kk][n]
    __shared__ __align__(16) float Xs[2][16 * SSTR];   // per-team [kk][m]

    const float* W = (blockIdx.y == 0) ? wq : ((blockIdx.y == 1) ? wk : wv);
    float* outp = g_QKV[blockIdx.y];

    const int tid  = threadIdx.x;
    const int team = tid >> 6;
    const int t    = tid & 63;
    const int rg   = t >> 3;      // 0..7 row group (8 rows)
    const int cg   = t & 7;       // 0..7 col group (cols 4cg..+3 and 32+4cg..+3)
    const int m0   = blockIdx.x * 128 + team * 64;

    float acc[8][8] = {};

    for (int k0 = 0; k0 < DIM; k0 += 16) {
        // Load W tile (whole block): 64 n x 16 k
        {
            int n  = tid >> 1;
            int kk = (tid & 1) * 8;
            float4 a = *(const float4*)(W + (size_t)n * DIM + k0 + kk);
            float4 c = *(const float4*)(W + (size_t)n * DIM + k0 + kk + 4);
            Ws[(kk + 0) * SSTR + n] = a.x;  Ws[(kk + 1) * SSTR + n] = a.y;
            Ws[(kk + 2) * SSTR + n] = a.z;  Ws[(kk + 3) * SSTR + n] = a.w;
            Ws[(kk + 4) * SSTR + n] = c.x;  Ws[(kk + 5) * SSTR + n] = c.y;
            Ws[(kk + 6) * SSTR + n] = c.z;  Ws[(kk + 7) * SSTR + n] = c.w;
        }
        // Load X tile per team: 64 rows x 16 k
        #pragma unroll
        for (int pass = 0; pass < 4; pass++) {
            int r  = pass * 16 + (t >> 2);
            int kk = (t & 3) * 4;
            float4 v = *(const float4*)(x + (size_t)(m0 + r) * DIM + k0 + kk);
            Xs[team][(kk + 0) * SSTR + r] = v.x;
            Xs[team][(kk + 1) * SSTR + r] = v.y;
            Xs[team][(kk + 2) * SSTR + r] = v.z;
            Xs[team][(kk + 3) * SSTR + r] = v.w;
        }
        __syncthreads();

        #pragma unroll 4
        for (int kk = 0; kk < 16; kk++) {
            float4 xa = *(const float4*)(Xs[team] + kk * SSTR + rg * 8);
            float4 xb = *(const float4*)(Xs[team] + kk * SSTR + rg * 8 + 4);
            float4 wa = *(const float4*)(Ws + kk * SSTR + cg * 4);
            float4 wb = *(const float4*)(Ws + kk * SSTR + 32 + cg * 4);
            float a[8] = {xa.x, xa.y, xa.z, xa.w, xb.x, xb.y, xb.z, xb.w};
            float b[8] = {wa.x, wa.y, wa.z, wa.w, wb.x, wb.y, wb.z, wb.w};
            #pragma unroll
            for (int i = 0; i < 8; i++)
                #pragma unroll
                for (int j = 0; j < 8; j++)
                    acc[i][j] = fmaf(a[i], b[j], acc[i][j]);
        }
        __syncthreads();
    }

    #pragma unroll
    for (int i = 0; i < 8; i++) {
        int row = m0 + rg * 8 + i;
        float4 o0 = {acc[i][0], acc[i][1], acc[i][2], acc[i][3]};
        float4 o1 = {acc[i][4], acc[i][5], acc[i][6], acc[i][7]};
        *(float4*)(outp + (size_t)row * HDIM + cg * 4)      = o0;
        *(float4*)(outp + (size_t)row * HDIM + 32 + cg * 4) = o1;
    }
}

// ---------------------------------------------------------------------------
// Flash attention: block 256 = 4 teams x 64. Each team handles interleaved
// quarter of KV tiles (split-K online softmax), merged at the end.
// Per thread: 8x8 S microtile + 8x8 O microtile. FMA:LDS ratio = 4.
// grid = (SEQ/64, BATCH). Dynamic smem 228352 B.
// ---------------------------------------------------------------------------
__global__ __launch_bounds__(256) void attn_kernel(float* __restrict__ out)
{
    extern __shared__ float sm[];
    float* Qs = sm;  // [d][i] transposed, shared by all teams

    const int tid  = threadIdx.x;
    const int team = tid >> 6;
    const int t    = tid & 63;
    const int rg   = t >> 3;
    const int cg   = t & 7;

    float* Ks = sm + TILE_F * (1 + team * 3);   // [d][j] transposed
    float* Vs = Ks + TILE_F;                    // [j][n] natural
    float* Ps = Vs + TILE_F;                    // [i][j] natural
    float* Ml = sm + TILE_F * 13;               // [team][{m,l}][64]

    const int b  = blockIdx.y;
    const int q0 = blockIdx.x * 64;

    const float* Qg = g_QKV[0] + (size_t)b * SEQ * HDIM;
    const float* Kg = g_QKV[1] + (size_t)b * SEQ * HDIM;
    const float* Vg = g_QKV[2] + (size_t)b * SEQ * HDIM;

    // Load Q tile transposed, scaled by 1/sqrt(64) (whole block)
    {
        int r  = tid >> 2;
        int c0 = (tid & 3) * 16;
        #pragma unroll
        for (int i = 0; i < 4; i++) {
            float4 v = *(const float4*)(Qg + (size_t)(q0 + r) * HDIM + c0 + i * 4);
            Qs[(c0 + i * 4 + 0) * SSTR + r] = v.x * 0.125f;
            Qs[(c0 + i * 4 + 1) * SSTR + r] = v.y * 0.125f;
            Qs[(c0 + i * 4 + 2) * SSTR + r] = v.z * 0.125f;
            Qs[(c0 + i * 4 + 3) * SSTR + r] = v.w * 0.125f;
        }
    }
    __syncthreads();

    float acc[8][8] = {};
    float mrow[8], lrow[8];
    #pragma unroll
    for (int i = 0; i < 8; i++) { mrow[i] = -1e30f; lrow[i] = 0.0f; }

    const int bar = team + 1;

    for (int it = 0; it < SEQ / 256; it++) {
        const int kt = team * 64 + it * 256;

        asm volatile("bar.sync %0, 64;" :: "r"(bar));  // prev PV reads done
        // Load K transposed + V natural (team-local)
        #pragma unroll
        for (int pass = 0; pass < 4; pass++) {
            int r  = pass * 16 + (t >> 2);
            int c0 = (t & 3) * 16;
            #pragma unroll
            for (int q = 0; q < 4; q++) {
                float4 kv = *(const float4*)(Kg + (size_t)(kt + r) * HDIM + c0 + q * 4);
                Ks[(c0 + q * 4 + 0) * SSTR + r] = kv.x;
                Ks[(c0 + q * 4 + 1) * SSTR + r] = kv.y;
                Ks[(c0 + q * 4 + 2) * SSTR + r] = kv.z;
                Ks[(c0 + q * 4 + 3) * SSTR + r] = kv.w;
                float4 vv = *(const float4*)(Vg + (size_t)(kt + r) * HDIM + c0 + q * 4);
                *(float4*)(Vs + r * SSTR + c0 + q * 4) = vv;
            }
        }
        asm volatile("bar.sync %0, 64;" :: "r"(bar));

        // S = Qscaled @ K^T : 8 rows x 8 cols per thread, cols {4cg..+3, 32+4cg..+3}
        float s[8][8] = {};
        #pragma unroll 8
        for (int d = 0; d < 64; d++) {
            float4 qa = *(const float4*)(Qs + d * SSTR + rg * 8);
            float4 qb = *(const float4*)(Qs + d * SSTR + rg * 8 + 4);
            float4 ka = *(const float4*)(Ks + d * SSTR + cg * 4);
            float4 kb = *(const float4*)(Ks + d * SSTR + 32 + cg * 4);
            float qv[8] = {qa.x, qa.y, qa.z, qa.w, qb.x, qb.y, qb.z, qb.w};
            float kv[8] = {ka.x, ka.y, ka.z, ka.w, kb.x, kb.y, kb.z, kb.w};
            #pragma unroll
            for (int i = 0; i < 8; i++)
                #pragma unroll
                for (int j = 0; j < 8; j++)
                    s[i][j] = fmaf(qv[i], kv[j], s[i][j]);
        }

        // Online softmax (row shared by the 8 cg threads; xor-shfl within group)
        #pragma unroll
        for (int i = 0; i < 8; i++) {
            float rm = s[i][0];
            #pragma unroll
            for (int j = 1; j < 8; j++) rm = fmaxf(rm, s[i][j]);
            rm = fmaxf(rm, __shfl_xor_sync(0xffffffffu, rm, 1));
            rm = fmaxf(rm, __shfl_xor_sync(0xffffffffu, rm, 2));
            rm = fmaxf(rm, __shfl_xor_sync(0xffffffffu, rm, 4));
            float nm   = fmaxf(mrow[i], rm);
            float corr = __expf(mrow[i] - nm);
            mrow[i] = nm;
            float rs = 0.0f;
            #pragma unroll
            for (int j = 0; j < 8; j++) {
                s[i][j] = __expf(s[i][j] - nm);
                rs += s[i][j];
            }
            rs += __shfl_xor_sync(0xffffffffu, rs, 1);
            rs += __shfl_xor_sync(0xffffffffu, rs, 2);
            rs += __shfl_xor_sync(0xffffffffu, rs, 4);
            lrow[i] = lrow[i] * corr + rs;
            #pragma unroll
            for (int j = 0; j < 8; j++) acc[i][j] *= corr;
        }

        // Store P
        #pragma unroll
        for (int i = 0; i < 8; i++) {
            int row = rg * 8 + i;
            float4 p0 = {s[i][0], s[i][1], s[i][2], s[i][3]};
            float4 p1 = {s[i][4], s[i][5], s[i][6], s[i][7]};
            *(float4*)(Ps + row * SSTR + cg * 4)      = p0;
            *(float4*)(Ps + row * SSTR + 32 + cg * 4) = p1;
        }
        asm volatile("bar.sync %0, 64;" :: "r"(bar));

        // O += P @ V : output cols {4cg..+3, 32+4cg..+3}
        #pragma unroll 8
        for (int j = 0; j < 64; j++) {
            float4 va = *(const float4*)(Vs + j * SSTR + cg * 4);
            float4 vb = *(const float4*)(Vs + j * SSTR + 32 + cg * 4);
            float vv[8] = {va.x, va.y, va.z, va.w, vb.x, vb.y, vb.z, vb.w};
            #pragma unroll
            for (int i = 0; i < 8; i++) {
                float p = Ps[(rg * 8 + i) * SSTR + j];
                #pragma unroll
                for (int n = 0; n < 8; n++)
                    acc[i][n] = fmaf(p, vv[n], acc[i][n]);
            }
        }
    }

    // Merge the 4 teams' partial (m, l, acc)
    __syncthreads();
    if (team > 0) {
        #pragma unroll
        for (int i = 0; i < 8; i++) {
            int row = rg * 8 + i;
            float4 a0 = {acc[i][0], acc[i][1], acc[i][2], acc[i][3]};
            float4 a1 = {acc[i][4], acc[i][5], acc[i][6], acc[i][7]};
            *(float4*)(Ks + row * SSTR + cg * 4)      = a0;   // reuse own Ks
            *(float4*)(Ks + row * SSTR + 32 + cg * 4) = a1;
            if (cg == 0) {
                Ml[team * 128 + row]      = mrow[i];
                Ml[team * 128 + 64 + row] = lrow[i];
            }
        }
    }
    __syncthreads();
    if (team == 0) {
        #pragma unroll
        for (int tm = 1; tm < 4; tm++) {
            float* A = sm + TILE_F * (1 + tm * 3);
            #pragma unroll
            for (int i = 0; i < 8; i++) {
                int row = rg * 8 + i;
                float m2 = Ml[tm * 128 + row];
                float l2 = Ml[tm * 128 + 64 + row];
                float M  = fmaxf(mrow[i], m2);
                float f1 = __expf(mrow[i] - M);
                float f2 = __expf(m2 - M);
                lrow[i] = lrow[i] * f1 + l2 * f2;
                float4 a0 = *(const float4*)(A + row * SSTR + cg * 4);
                float4 a1 = *(const float4*)(A + row * SSTR + 32 + cg * 4);
                acc[i][0] = acc[i][0] * f1 + a0.x * f2;
                acc[i][1] = acc[i][1] * f1 + a0.y * f2;
                acc[i][2] = acc[i][2] * f1 + a0.z * f2;
                acc[i][3] = acc[i][3] * f1 + a0.w * f2;
                acc[i][4] = acc[i][4] * f1 + a1.x * f2;
                acc[i][5] = acc[i][5] * f1 + a1.y * f2;
                acc[i][6] = acc[i][6] * f1 + a1.z * f2;
                acc[i][7] = acc[i][7] * f1 + a1.w * f2;
                mrow[i] = M;
            }
        }
        #pragma unroll
        for (int i = 0; i < 8; i++) {
            int row = rg * 8 + i;
            float inv = 1.0f / lrow[i];
            float4 o0 = {acc[i][0] * inv, acc[i][1] * inv, acc[i][2] * inv, acc[i][3] * inv};
            float4 o1 = {acc[i][4] * inv, acc[i][5] * inv, acc[i][6] * inv, acc[i][7] * inv};
            float* op = out + ((size_t)b * SEQ + q0 + row) * HDIM;
            *(float4*)(op + cg * 4)      = o0;
            *(float4*)(op + 32 + cg * 4) = o1;
        }
    }
}

// ---------------------------------------------------------------------------
extern "C" void kernel_launch(void* const* d_in, const int* in_sizes, int n_in,
                              void* d_out, int out_size)
{
    const float* x  = (const float*)d_in[0];
    const float* wq = (const float*)d_in[1];
    const float* wk = (const float*)d_in[2];
    const float* wv = (const float*)d_in[3];
    float* out = (float*)d_out;

    qkv_kernel<<<dim3((BATCH * SEQ) / 128, 3), 128>>>(x, wq, wk, wv);

    const int smem = (TILE_F * 13 + 4 * 128) * (int)sizeof(float);  // 228352
    cudaFuncSetAttribute(attn_kernel, cudaFuncAttributeMaxDynamicSharedMemorySize, smem);
    attn_kernel<<<dim3(SEQ / 64, BATCH), 256, smem>>>(out);
}

// round 5
// speedup vs baseline: 1.9250x; 1.5745x over previous
#include <cuda_runtime.h>
#include <cuda_bf16.h>
#include <math.h>
#include <stdint.h>

#define BATCH 4
#define SEQ   4096
#define DIM   1024
#define HDIM  64

#define SSTR   68

__device__ float g_QKV[3][(size_t)BATCH * SEQ * HDIM];

// ===================== helpers =====================
__device__ __forceinline__ uint32_t smem_u32(const void* p) {
    uint32_t a;
    asm("{ .reg .u64 t; cvta.to.shared.u64 t, %1; cvt.u32.u64 %0, t; }" : "=r"(a) : "l"(p));
    return a;
}

// split fp32 pair -> bf16x2 hi word (low half = first value) + bf16x2 residual word
__device__ __forceinline__ void cvt_pair(float a, float b, uint32_t& hi, uint32_t& lo) {
    __nv_bfloat16 ah = __float2bfloat16(a);
    __nv_bfloat16 bh = __float2bfloat16(b);
    float ar = a - __bfloat162float(ah);
    float br = b - __bfloat162float(bh);
    __nv_bfloat162 H = __halves2bfloat162(ah, bh);
    __nv_bfloat162 L = __halves2bfloat162(__float2bfloat16(ar), __float2bfloat16(br));
    hi = *reinterpret_cast<uint32_t*>(&H);
    lo = *reinterpret_cast<uint32_t*>(&L);
}

#define LDSM_X4(r0, r1, r2, r3, addr) \
    asm volatile("ldmatrix.sync.aligned.m8n8.x4.shared.b16 {%0,%1,%2,%3}, [%4];" \
        : "=r"(r0), "=r"(r1), "=r"(r2), "=r"(r3) : "r"(addr))
#define LDSM_X2(r0, r1, addr) \
    asm volatile("ldmatrix.sync.aligned.m8n8.x2.shared.b16 {%0,%1}, [%2];" \
        : "=r"(r0), "=r"(r1) : "r"(addr))

#define MMA16816(d, a, b) \
    asm volatile("mma.sync.aligned.m16n8k16.row.col.f32.bf16.bf16.f32 " \
        "{%0,%1,%2,%3}, {%4,%5,%6,%7}, {%8,%9}, {%0,%1,%2,%3};" \
        : "+f"((d)[0]), "+f"((d)[1]), "+f"((d)[2]), "+f"((d)[3]) \
        : "r"((a)[0]), "r"((a)[1]), "r"((a)[2]), "r"((a)[3]), "r"((b)[0]), "r"((b)[1]))

// smem byte offsets; all tiles stride 72 bf16 = 144 B per row
#define RSTR    144
#define KH_OFF  0
#define KL_OFF  9216
#define VH_OFF  18432
#define VL_OFF  27648
#define QH_OFF  0          // Q phase aliases K/V region (used before first K/V store)
#define QL_OFF  18432
#define SM_BYTES 36864

// ---------------------------------------------------------------------------
// QKV projection (SIMT fp32, near FMA roofline)
// ---------------------------------------------------------------------------
__global__ __launch_bounds__(128) void qkv_kernel(
    const float* __restrict__ x, const float* __restrict__ wq,
    const float* __restrict__ wk, const float* __restrict__ wv)
{
    __shared__ __align__(16) float Ws[16 * SSTR];
    __shared__ __align__(16) float Xs[2][16 * SSTR];

    const float* W = (blockIdx.y == 0) ? wq : ((blockIdx.y == 1) ? wk : wv);
    float* outp = g_QKV[blockIdx.y];

    const int tid = threadIdx.x, team = tid >> 6, t = tid & 63;
    const int rg = t >> 3, cg = t & 7;
    const int m0 = blockIdx.x * 128 + team * 64;

    float acc[8][8] = {};
    for (int k0 = 0; k0 < DIM; k0 += 16) {
        {
            int n = tid >> 1, kk = (tid & 1) * 8;
            float4 a = *(const float4*)(W + (size_t)n * DIM + k0 + kk);
            float4 c = *(const float4*)(W + (size_t)n * DIM + k0 + kk + 4);
            Ws[(kk + 0) * SSTR + n] = a.x;  Ws[(kk + 1) * SSTR + n] = a.y;
            Ws[(kk + 2) * SSTR + n] = a.z;  Ws[(kk + 3) * SSTR + n] = a.w;
            Ws[(kk + 4) * SSTR + n] = c.x;  Ws[(kk + 5) * SSTR + n] = c.y;
            Ws[(kk + 6) * SSTR + n] = c.z;  Ws[(kk + 7) * SSTR + n] = c.w;
        }
        #pragma unroll
        for (int pass = 0; pass < 4; pass++) {
            int r = pass * 16 + (t >> 2), kk = (t & 3) * 4;
            float4 v = *(const float4*)(x + (size_t)(m0 + r) * DIM + k0 + kk);
            Xs[team][(kk + 0) * SSTR + r] = v.x;
            Xs[team][(kk + 1) * SSTR + r] = v.y;
            Xs[team][(kk + 2) * SSTR + r] = v.z;
            Xs[team][(kk + 3) * SSTR + r] = v.w;
        }
        __syncthreads();
        #pragma unroll 4
        for (int kk = 0; kk < 16; kk++) {
            float4 xa = *(const float4*)(Xs[team] + kk * SSTR + rg * 8);
            float4 xb = *(const float4*)(Xs[team] + kk * SSTR + rg * 8 + 4);
            float4 wa = *(const float4*)(Ws + kk * SSTR + cg * 4);
            float4 wb = *(const float4*)(Ws + kk * SSTR + 32 + cg * 4);
            float a[8] = {xa.x, xa.y, xa.z, xa.w, xb.x, xb.y, xb.z, xb.w};
            float b[8] = {wa.x, wa.y, wa.z, wa.w, wb.x, wb.y, wb.z, wb.w};
            #pragma unroll
            for (int i = 0; i < 8; i++)
                #pragma unroll
                for (int j = 0; j < 8; j++)
                    acc[i][j] = fmaf(a[i], b[j], acc[i][j]);
        }
        __syncthreads();
    }
    #pragma unroll
    for (int i = 0; i < 8; i++) {
        int row = m0 + rg * 8 + i;
        float4 o0 = {acc[i][0], acc[i][1], acc[i][2], acc[i][3]};
        float4 o1 = {acc[i][4], acc[i][5], acc[i][6], acc[i][7]};
        *(float4*)(outp + (size_t)row * HDIM + cg * 4)      = o0;
        *(float4*)(outp + (size_t)row * HDIM + 32 + cg * 4) = o1;
    }
}

// ---------------------------------------------------------------------------
// FA2 attention via mma.sync (HMMA), bf16 hi/lo 3-term.
// CTA: 256 threads = 8 warps. Q tile 128 rows (16/warp). KV tile 64.
// K smem [key][hd], V smem transposed [hd][key], both hi+lo, stride 72 bf16.
// grid = (SEQ/128, BATCH).
// ---------------------------------------------------------------------------
__global__ __launch_bounds__(256) void attn_kernel(float* __restrict__ out)
{
    __shared__ __align__(16) char sm[SM_BYTES];

    const int tid = threadIdx.x;
    const int w = tid >> 5, l = tid & 31;
    const int b = blockIdx.y;
    const int q0 = blockIdx.x * 128;

    const float* Qg = g_QKV[0] + (size_t)b * SEQ * HDIM;
    const float* Kg = g_QKV[1] + (size_t)b * SEQ * HDIM;
    const float* Vg = g_QKV[2] + (size_t)b * SEQ * HDIM;

    // ---- Q tile -> smem (hi/lo, scaled by 0.125)
    {
        int r = tid >> 1, c0 = (tid & 1) * 32;
        const float* qr = Qg + (size_t)(q0 + r) * HDIM + c0;
        #pragma unroll
        for (int q = 0; q < 8; q++) {
            float4 v = *(const float4*)(qr + q * 4);
            uint32_t h0, l0w, h1, l1w;
            cvt_pair(v.x * 0.125f, v.y * 0.125f, h0, l0w);
            cvt_pair(v.z * 0.125f, v.w * 0.125f, h1, l1w);
            uint32_t off = (uint32_t)r * RSTR + (uint32_t)(c0 + q * 4) * 2;
            *(uint32_t*)(sm + QH_OFF + off)     = h0;
            *(uint32_t*)(sm + QH_OFF + off + 4) = h1;
            *(uint32_t*)(sm + QL_OFF + off)     = l0w;
            *(uint32_t*)(sm + QL_OFF + off + 4) = l1w;
        }
    }
    __syncthreads();

    // ---- extract Q fragments (held in regs for the whole kernel)
    uint32_t qh[4][4], ql[4][4];
    {
        uint32_t rowb = (uint32_t)(16 * w + (l & 15)) * RSTR + (uint32_t)((l >> 4) * 8) * 2;
        #pragma unroll
        for (int kk = 0; kk < 4; kk++) {
            uint32_t ah = smem_u32(sm + QH_OFF + rowb + kk * 32);
            uint32_t al = smem_u32(sm + QL_OFF + rowb + kk * 32);
            LDSM_X4(qh[kk][0], qh[kk][1], qh[kk][2], qh[kk][3], ah);
            LDSM_X4(ql[kk][0], ql[kk][1], ql[kk][2], ql[kk][3], al);
        }
    }
    __syncthreads();   // Q region free for K/V reuse

    float o[8][4];
    #pragma unroll
    for (int j = 0; j < 8; j++)
        #pragma unroll
        for (int c = 0; c < 4; c++) o[j][c] = 0.0f;
    float m0r = -1e30f, m1r = -1e30f, l0r = 0.0f, l1r = 0.0f;

    for (int it = 0; it < SEQ / 64; it++) {
        const int kt = it * 64;

        // ---- K tile -> smem [key][hd] hi/lo
        {
            int r = tid >> 2, c0 = (tid & 3) * 16;
            const float* kr = Kg + (size_t)(kt + r) * HDIM + c0;
            #pragma unroll
            for (int q = 0; q < 4; q++) {
                float4 v = *(const float4*)(kr + q * 4);
                uint32_t h0, l0w, h1, l1w;
                cvt_pair(v.x, v.y, h0, l0w);
                cvt_pair(v.z, v.w, h1, l1w);
                uint32_t off = (uint32_t)r * RSTR + (uint32_t)(c0 + q * 4) * 2;
                *(uint32_t*)(sm + KH_OFF + off)     = h0;
                *(uint32_t*)(sm + KH_OFF + off + 4) = h1;
                *(uint32_t*)(sm + KL_OFF + off)     = l0w;
                *(uint32_t*)(sm + KL_OFF + off + 4) = l1w;
            }
        }
        // ---- V tile -> smem transposed [hd][key] hi/lo
        {
            int j0 = (tid & 31) * 2;
            int d0 = (tid >> 5) * 8;
            const float* v0p = Vg + (size_t)(kt + j0) * HDIM + d0;
            const float* v1p = v0p + HDIM;
            float a0[8], a1[8];
            *(float4*)(a0)     = *(const float4*)(v0p);
            *(float4*)(a0 + 4) = *(const float4*)(v0p + 4);
            *(float4*)(a1)     = *(const float4*)(v1p);
            *(float4*)(a1 + 4) = *(const float4*)(v1p + 4);
            #pragma unroll
            for (int d = 0; d < 8; d++) {
                uint32_t hi, lo;
                cvt_pair(a0[d], a1[d], hi, lo);   // (V[j0][d], V[j0+1][d])
                uint32_t off = (uint32_t)(d0 + d) * RSTR + (uint32_t)j0 * 2;
                *(uint32_t*)(sm + VH_OFF + off) = hi;
                *(uint32_t*)(sm + VL_OFF + off) = lo;
            }
        }
        __syncthreads();

        // ---- S = Q @ K^T : per warp 16 x 64, 3-term
        float s[8][4];
        #pragma unroll
        for (int j = 0; j < 8; j++) {
            s[j][0] = s[j][1] = s[j][2] = s[j][3] = 0.0f;
            uint32_t rowb = (uint32_t)(8 * j + (l & 7)) * RSTR + (uint32_t)(((l >> 3) & 1) * 8) * 2;
            #pragma unroll
            for (int kk = 0; kk < 4; kk++) {
                uint32_t bh[2], bl[2];
                LDSM_X2(bh[0], bh[1], smem_u32(sm + KH_OFF + rowb + kk * 32));
                LDSM_X2(bl[0], bl[1], smem_u32(sm + KL_OFF + rowb + kk * 32));
                MMA16816(s[j], qh[kk], bh);
                MMA16816(s[j], qh[kk], bl);
                MMA16816(s[j], ql[kk], bh);
            }
        }

        // ---- online softmax (rows r0 = l/4, r1 = l/4 + 8; reduce over 4 lanes)
        float rm0 = m0r, rm1 = m1r;
        #pragma unroll
        for (int j = 0; j < 8; j++) {
            rm0 = fmaxf(rm0, fmaxf(s[j][0], s[j][1]));
            rm1 = fmaxf(rm1, fmaxf(s[j][2], s[j][3]));
        }
        rm0 = fmaxf(rm0, __shfl_xor_sync(0xffffffffu, rm0, 1));
        rm0 = fmaxf(rm0, __shfl_xor_sync(0xffffffffu, rm0, 2));
        rm1 = fmaxf(rm1, __shfl_xor_sync(0xffffffffu, rm1, 1));
        rm1 = fmaxf(rm1, __shfl_xor_sync(0xffffffffu, rm1, 2));
        float c0f = __expf(m0r - rm0), c1f = __expf(m1r - rm1);
        m0r = rm0;  m1r = rm1;
        float ls0 = 0.0f, ls1 = 0.0f;
        #pragma unroll
        for (int j = 0; j < 8; j++) {
            s[j][0] = __expf(s[j][0] - rm0);
            s[j][1] = __expf(s[j][1] - rm0);
            s[j][2] = __expf(s[j][2] - rm1);
            s[j][3] = __expf(s[j][3] - rm1);
            ls0 += s[j][0] + s[j][1];
            ls1 += s[j][2] + s[j][3];
            o[j][0] *= c0f;  o[j][1] *= c0f;
            o[j][2] *= c1f;  o[j][3] *= c1f;
        }
        ls0 += __shfl_xor_sync(0xffffffffu, ls0, 1);
        ls0 += __shfl_xor_sync(0xffffffffu, ls0, 2);
        ls1 += __shfl_xor_sync(0xffffffffu, ls1, 1);
        ls1 += __shfl_xor_sync(0xffffffffu, ls1, 2);
        l0r = l0r * c0f + ls0;
        l1r = l1r * c1f + ls1;

        // ---- O += P @ V (P hi/lo packed from s, V from transposed smem)
        #pragma unroll
        for (int kk = 0; kk < 4; kk++) {
            uint32_t ah[4], al[4];
            cvt_pair(s[2 * kk][0],     s[2 * kk][1],     ah[0], al[0]);
            cvt_pair(s[2 * kk][2],     s[2 * kk][3],     ah[1], al[1]);
            cvt_pair(s[2 * kk + 1][0], s[2 * kk + 1][1], ah[2], al[2]);
            cvt_pair(s[2 * kk + 1][2], s[2 * kk + 1][3], ah[3], al[3]);
            #pragma unroll
            for (int j = 0; j < 8; j++) {
                uint32_t rowb = (uint32_t)(8 * j + (l & 7)) * RSTR + (uint32_t)(kk * 16 + ((l >> 3) & 1) * 8) * 2;
                uint32_t vh[2], vl[2];
                LDSM_X2(vh[0], vh[1], smem_u32(sm + VH_OFF + rowb));
                LDSM_X2(vl[0], vl[1], smem_u32(sm + VL_OFF + rowb));
                MMA16816(o[j], ah, vh);
                MMA16816(o[j], ah, vl);
                MMA16816(o[j], al, vh);
            }
        }
        __syncthreads();   // all reads done before next iter's smem stores
    }

    // ---- epilogue
    {
        float inv0 = 1.0f / l0r, inv1 = 1.0f / l1r;
        int r0 = q0 + 16 * w + (l >> 2);
        int col = 2 * (l & 3);
        float* op0 = out + ((size_t)b * SEQ + r0) * HDIM;
        float* op1 = op0 + 8 * HDIM;
        #pragma unroll
        for (int j = 0; j < 8; j++) {
            float2 v0 = {o[j][0] * inv0, o[j][1] * inv0};
            float2 v1 = {o[j][2] * inv1, o[j][3] * inv1};
            *(float2*)(op0 + 8 * j + col) = v0;
            *(float2*)(op1 + 8 * j + col) = v1;
        }
    }
}

// ---------------------------------------------------------------------------
extern "C" void kernel_launch(void* const* d_in, const int* in_sizes, int n_in,
                              void* d_out, int out_size)
{
    const float* x  = (const float*)d_in[0];
    const float* wq = (const float*)d_in[1];
    const float* wk = (const float*)d_in[2];
    const float* wv = (const float*)d_in[3];
    float* out = (float*)d_out;

    qkv_kernel<<<dim3((BATCH * SEQ) / 128, 3), 128>>>(x, wq, wk, wv);
    attn_kernel<<<dim3(SEQ / 128, BATCH), 256>>>(out);
}